// round 8
// baseline (speedup 1.0000x reference)
#include <cuda_runtime.h>
#include <math.h>

#define NB 16
#define NT 128
#define NC 64
#define NU 128
#define UNF 6
#define EPSV 1e-8f
#define TCHUNK 16

#define RANKS 8               // CTAs per cluster (per batch element)
#define JPC (NU / RANKS)      // 16 post-units per CTA
#define TPJ (128 / JPC)       // 8 threads per post-unit
#define PRE (NU / TPJ)        // 16 pre-units per thread
#define TXB (NU * 4)          // 512 bytes of v per unfold per rank

// Scratch (allocation-free rule: __device__ globals)
__device__ float g_sensN[NB * NT * NU];
__device__ float g_sensD[NB * NT * NU];
__device__ float g_SA[NC * NU];
__device__ float g_SB[NC * NU];
__device__ float g_SW[NC * NU];

__device__ __forceinline__ float tanha(float x) {
    float r;
    asm("tanh.approx.f32 %0, %1;" : "=f"(r) : "f"(x));
    return r;
}

__device__ __forceinline__ float softplusf(float x) {
    return log1pf(__expf(x));
}

__device__ __forceinline__ unsigned smem_u32(const void* p) {
    unsigned a;
    asm("{ .reg .u64 t; cvta.to.shared.u64 t, %1; cvt.u32.u64 %0, t; }"
        : "=r"(a) : "l"(p));
    return a;
}

__device__ __forceinline__ void mbar_wait(unsigned addr, unsigned phase) {
    unsigned done;
    asm volatile(
        "{\n\t"
        ".reg .pred p;\n\t"
        "mbarrier.try_wait.parity.acquire.cluster.shared::cta.b64 p, [%1], %2, 0x989680;\n\t"
        "selp.b32 %0, 1, 0, p;\n\t"
        "}"
        : "=r"(done) : "r"(addr), "r"(phase) : "memory");
    if (!done) {
        asm volatile(
            "{\n\t"
            ".reg .pred P1;\n\t"
            "WLT_%=:\n\t"
            "mbarrier.try_wait.parity.acquire.cluster.shared::cta.b64 P1, [%0], %1, 0x989680;\n\t"
            "@P1 bra.uni WDN_%=;\n\t"
            "bra.uni WLT_%=;\n\t"
            "WDN_%=:\n\t"
            "}"
            :: "r"(addr), "r"(phase) : "memory");
    }
}

// ---------------------------------------------------------------------------
// Kernel 0: transform sensory params once (fp32)
// ---------------------------------------------------------------------------
__global__ void k_sens_prep(const float* __restrict__ ss,
                            const float* __restrict__ smu,
                            const float* __restrict__ sw,
                            const float* __restrict__ serev) {
    int idx = blockIdx.x * blockDim.x + threadIdx.x;
    if (idx < NC * NU) {
        float a = 0.5f * ss[idx];
        g_SA[idx] = a;
        g_SB[idx] = -a * smu[idx];
        g_SW[idx] = softplusf(sw[idx]) * serev[idx];
    }
}

// ---------------------------------------------------------------------------
// Kernel 1: sensory pre-pass (fp32, fully parallel over b,t)
// ---------------------------------------------------------------------------
__global__ void __launch_bounds__(128) k_sensory(const float* __restrict__ x,
                                                 const float* __restrict__ iw,
                                                 const float* __restrict__ ib) {
    extern __shared__ float sm[];
    float* sSA = sm;
    float* sSB = sm + NC * NU;
    float* sSW = sm + 2 * NC * NU;
    float* xb  = sm + 3 * NC * NU;  // TCHUNK*NC

    int b  = blockIdx.x / (NT / TCHUNK);
    int t0 = (blockIdx.x % (NT / TCHUNK)) * TCHUNK;
    int tid = threadIdx.x;

    for (int idx = tid; idx < NC * NU; idx += 128) {
        sSA[idx] = g_SA[idx];
        sSB[idx] = g_SB[idx];
        sSW[idx] = g_SW[idx];
    }
    for (int idx = tid; idx < TCHUNK * NC; idx += 128) {
        int tt = idx / NC, i = idx % NC;
        xb[idx] = fmaf(x[(b * NT + t0 + tt) * NC + i], iw[i], ib[i]);
    }
    __syncthreads();

    int j = tid;
    for (int tt = 0; tt < TCHUNK; tt++) {
        float wn = 0.f, wd = 0.f;
#pragma unroll 8
        for (int i = 0; i < NC; i++) {
            float xv = xb[tt * NC + i];
            float y  = fmaf(sSA[i * NU + j], xv, sSB[i * NU + j]);
            float s  = fmaf(0.5f, tanha(y), 0.5f);
            float we = sSW[i * NU + j];
            wn = fmaf(we, s, wn);
            wd = fmaf(fabsf(we), s, wd);
        }
        int o = (b * NT + t0 + tt) * NU + j;
        g_sensN[o] = wn;
        g_sensD[o] = wd;
    }
}

// ---------------------------------------------------------------------------
// Kernel 2: main recurrence. 8-CTA cluster per batch element.
// CTA `rank` owns post-units [rank*16, rank*16+16). Thread t: jloc=t/8,
// oct=t%8; post-unit j = rank*16+jloc over pre-units [oct*16, oct*16+16).
// Per unfold (st.async transaction-barrier protocol, no __syncthreads):
//   - thread 0 arms the unfold's local mbarrier: arrive.expect_tx(512B)
//   - compute (16 tanh/thread), 3-level shfl reduction -> every lane of an
//     8-lane group holds the group's final v
//   - SENDERS (t%16==0) fetch neighbor group's v via shfl_down(8), pack two
//     fp32 into b64, and issue ONE st.async.b64 per rank (8 stores); each
//     8B store counts down the destination's tx. 64 tx-updates per barrier
//     per unfold (vs 128 with f32) -- halves the barrier-update serialization.
//   - all threads try_wait.parity.acquire on the LOCAL barrier.
// Race-freedom as in R7: a CTA passes barrier u only after all 128 v bytes
// landed; stores are issued after the group's shfl (old-buffer reads done),
// so next-unfold writes can't overtake reads. Two ping-pong barriers.
// ---------------------------------------------------------------------------
__global__ void __launch_bounds__(128, 1) __cluster_dims__(RANKS, 1, 1)
k_main(const float* __restrict__ h0,
       const float* __restrict__ gleak,
       const float* __restrict__ vleak,
       const float* __restrict__ cm,
       const float* __restrict__ sigma,
       const float* __restrict__ mu,
       const float* __restrict__ w,
       const float* __restrict__ erev,
       const float* __restrict__ ow,
       const float* __restrict__ ob,
       float* __restrict__ out,
       int write_hfinal) {
    __shared__ float vsm[2 * NU];
    __shared__ alignas(16) unsigned long long mbar[2];

    int rank = blockIdx.x;
    int b    = blockIdx.y;
    int t    = threadIdx.x;
    int jloc = t / TPJ;
    int oct  = t % TPJ;
    int j    = rank * JPC + jloc;

    // ---- Prologue: this thread's 16 pre-unit params into registers ----
    // 0.5 factor folded into the weights.
    float pa[PRE], pb[PRE], pw[PRE], pq[PRE];
    float swe = 0.f, swa = 0.f;
#pragma unroll
    for (int k = 0; k < PRE; k++) {
        int i   = oct * PRE + k;
        int idx = i * NU + j;
        float sg = sigma[idx];
        pa[k] = 0.5f * sg;
        pb[k] = -pa[k] * mu[idx];
        float ww = 0.5f * softplusf(w[idx]) * erev[idx];
        pw[k] = ww;
        pq[k] = fabsf(ww);
        swe += ww;
        swa += pq[k];
    }
    swe += __shfl_xor_sync(0xFFFFFFFFu, swe, 1);
    swe += __shfl_xor_sync(0xFFFFFFFFu, swe, 2);
    swe += __shfl_xor_sync(0xFFFFFFFFu, swe, 4);
    swa += __shfl_xor_sync(0xFFFFFFFFu, swa, 1);
    swa += __shfl_xor_sync(0xFFFFFFFFu, swa, 2);
    swa += __shfl_xor_sync(0xFFFFFFFFu, swa, 4);

    float gl  = softplusf(gleak[j]);
    float cmt = softplusf(cm[j]) * (float)UNF;
    float K1  = fmaf(gl, vleak[j], swe);           // swe already carries 0.5
    float K2  = cmt + gl + swa + EPSV;
    float owj = ow[j], obj = ob[j];

    // init v buffer 0 with h0 (local copy per CTA); init both mbarriers
    vsm[t] = h0[b * NU + t];
    if (t == 0) {
        asm volatile("mbarrier.init.shared.b64 [%0], %1;"
                     :: "r"(smem_u32(&mbar[0])), "r"(1) : "memory");
        asm volatile("mbarrier.init.shared.b64 [%0], %1;"
                     :: "r"(smem_u32(&mbar[1])), "r"(1) : "memory");
    }
    __syncthreads();
    float vloc = vsm[j];

    // peer addresses for all 8 ranks
    unsigned vbase = smem_u32(vsm);
    unsigned b0 = smem_u32(&mbar[0]);
    unsigned b1 = smem_u32(&mbar[1]);
    unsigned peerV[RANKS], peerB0[RANKS], peerB1[RANKS];
#pragma unroll
    for (int r = 0; r < RANKS; r++) {
        asm("mapa.shared::cluster.u32 %0, %1, %2;"
            : "=r"(peerV[r]) : "r"(vbase), "r"(r));
        asm("mapa.shared::cluster.u32 %0, %1, %2;"
            : "=r"(peerB0[r]) : "r"(b0), "r"(r));
        asm("mapa.shared::cluster.u32 %0, %1, %2;"
            : "=r"(peerB1[r]) : "r"(b1), "r"(r));
    }

    // all mbarriers initialized before any remote store/complete_tx
    asm volatile("barrier.cluster.arrive.aligned;" ::: "memory");
    asm volatile("barrier.cluster.wait.aligned;" ::: "memory");

    unsigned ph0 = 0, ph1 = 0;
    int bsel = 0;
    int p = 0;

    int sender = ((t & 15) == 0);

    // prefetch sensory terms for t=0
    int so = (b * NT) * NU + j;
    float curN = g_sensN[so];
    float curD = g_sensD[so];

#pragma unroll 1
    for (int ts = 0; ts < NT; ts++) {
        float base_n = K1 + curN;
        float base_d = K2 + curD;
        if (ts + 1 < NT) {
            curN = g_sensN[so + NU];
            curD = g_sensD[so + NU];
        }
#pragma unroll 1
        for (int u = 0; u < UNF; u++) {
            // arm this unfold's barrier early (1 arrival + 512B expected)
            if (t == 0) {
                unsigned bb = bsel ? b1 : b0;
                asm volatile(
                    "mbarrier.arrive.expect_tx.shared.b64 _, [%0], %1;"
                    :: "r"(bb), "r"(TXB) : "memory");
            }

            const float4* v4 = (const float4*)(vsm + p * NU + oct * PRE);
            float q = 0.f, r = 0.f;
#pragma unroll
            for (int c = 0; c < PRE / 4; c++) {
                float4 vv = v4[c];
                float t0 = tanha(fmaf(pa[4 * c + 0], vv.x, pb[4 * c + 0]));
                float t1 = tanha(fmaf(pa[4 * c + 1], vv.y, pb[4 * c + 1]));
                float t2 = tanha(fmaf(pa[4 * c + 2], vv.z, pb[4 * c + 2]));
                float t3 = tanha(fmaf(pa[4 * c + 3], vv.w, pb[4 * c + 3]));
                q = fmaf(pw[4 * c + 0], t0, q);
                r = fmaf(pq[4 * c + 0], t0, r);
                q = fmaf(pw[4 * c + 1], t1, q);
                r = fmaf(pq[4 * c + 1], t1, r);
                q = fmaf(pw[4 * c + 2], t2, q);
                r = fmaf(pq[4 * c + 2], t2, r);
                q = fmaf(pw[4 * c + 3], t3, q);
                r = fmaf(pq[4 * c + 3], t3, r);
            }
            q += __shfl_xor_sync(0xFFFFFFFFu, q, 1);
            q += __shfl_xor_sync(0xFFFFFFFFu, q, 2);
            q += __shfl_xor_sync(0xFFFFFFFFu, q, 4);
            r += __shfl_xor_sync(0xFFFFFFFFu, r, 1);
            r += __shfl_xor_sync(0xFFFFFFFFu, r, 2);
            r += __shfl_xor_sync(0xFFFFFFFFu, r, 4);

            float num = fmaf(cmt, vloc, base_n) + q;
            float den = base_d + r;
            vloc = __fdividef(num, den);

            // neighbor group's v (group jloc+1 lives 8 lanes down)
            float vhi = __shfl_down_sync(0xFFFFFFFFu, vloc, 8);

            // senders: pack (v_j, v_j+1) into b64, one st.async per rank
            if (sender) {
                unsigned long long pk =
                    ((unsigned long long)__float_as_uint(vhi) << 32) |
                    (unsigned long long)__float_as_uint(vloc);
                unsigned off = (unsigned)(((p ^ 1) * NU + j) * 4);
                if (bsel == 0) {
#pragma unroll
                    for (int rr = 0; rr < RANKS; rr++) {
                        asm volatile(
                            "st.async.shared::cluster.mbarrier::complete_tx::bytes.b64 "
                            "[%0], %1, [%2];"
                            :: "r"(peerV[rr] + off), "l"(pk), "r"(peerB0[rr])
                            : "memory");
                    }
                } else {
#pragma unroll
                    for (int rr = 0; rr < RANKS; rr++) {
                        asm volatile(
                            "st.async.shared::cluster.mbarrier::complete_tx::bytes.b64 "
                            "[%0], %1, [%2];"
                            :: "r"(peerV[rr] + off), "l"(pk), "r"(peerB1[rr])
                            : "memory");
                    }
                }
            }
            // wait for all 128 v's (512B) to land in the LOCAL buffer
            if (bsel == 0) {
                mbar_wait(b0, ph0);
                ph0 ^= 1;
            } else {
                mbar_wait(b1, ph1);
                ph1 ^= 1;
            }
            bsel ^= 1;
            p ^= 1;
        }
        if (oct == 0) {
            out[so] = fmaf(vloc, owj, obj);
        }
        so += NU;
    }
    if (write_hfinal && oct == 0) {
        out[NB * NT * NU + b * NU + j] = vloc;
    }

    // no CTA may exit while peers' remote ops could still target its smem
    asm volatile("barrier.cluster.arrive.aligned;" ::: "memory");
    asm volatile("barrier.cluster.wait.aligned;" ::: "memory");
}

// ---------------------------------------------------------------------------
extern "C" void kernel_launch(void* const* d_in, const int* in_sizes, int n_in,
                              void* d_out, int out_size) {
    const float* x      = (const float*)d_in[0];
    const float* h0     = (const float*)d_in[1];
    const float* gleak  = (const float*)d_in[2];
    const float* vleak  = (const float*)d_in[3];
    const float* cm     = (const float*)d_in[4];
    const float* sigma  = (const float*)d_in[5];
    const float* mu     = (const float*)d_in[6];
    const float* w      = (const float*)d_in[7];
    const float* erev   = (const float*)d_in[8];
    const float* ss     = (const float*)d_in[9];
    const float* smu    = (const float*)d_in[10];
    const float* sw     = (const float*)d_in[11];
    const float* serev  = (const float*)d_in[12];
    const float* iw     = (const float*)d_in[13];
    const float* ibias  = (const float*)d_in[14];
    const float* outw   = (const float*)d_in[15];
    const float* outb   = (const float*)d_in[16];

    const int SENS_SMEM = (3 * NC * NU + TCHUNK * NC) * (int)sizeof(float);  // 100 KB
    cudaFuncSetAttribute(k_sensory, cudaFuncAttributeMaxDynamicSharedMemorySize, SENS_SMEM);

    int write_hfinal = (out_size >= NB * NT * NU + NB * NU) ? 1 : 0;

    k_sens_prep<<<(NC * NU + 255) / 256, 256>>>(ss, smu, sw, serev);
    k_sensory<<<NB * (NT / TCHUNK), 128, SENS_SMEM>>>(x, iw, ibias);

    dim3 grid(RANKS, NB);
    k_main<<<grid, 128>>>(h0, gleak, vleak, cm, sigma, mu, w, erev,
                          outw, outb, (float*)d_out, write_hfinal);
}